// round 16
// baseline (speedup 1.0000x reference)
#include <cuda_runtime.h>
#include <cstdint>

#define N_NODES 5000
#define N_EDGES 50000
#define D 64
#define EDIM 16
#define NCHUNK 65                          // 64 W2 chunks + 1 bias chunk
#define GROW 4160                          // G row words: 65 chunks * 64
#define BS_STRIDE 72                       // padded B j-row stride (words)
#define BS_CHUNK (64 * BS_STRIDE)          // 4608 words per staged B chunk
#define AS_STRIDE 68                       // padded A row stride (words)
#define NTILE 40                           // ceil(5000/128) node tiles
#define NSEG 7                             // K segments: 5x9 + 2x10 chunks = 65; 280 CTAs (1 wave)
#define MLP_BLOCKS 782                     // ceil(50000/64)
#define BB_BLOCKS 1250                     // ceil(320000/256) covers 266240 too
#define BKT_CAP 64                         // per-target bucket capacity (deg~Poisson(10))

// ---------------- scratch (static device globals; no allocation) ----------------
__device__ float g_hid[N_EDGES * D];       // relu(ef@W1+b1)
__device__ float g_B[NCHUNK * 4096];       // tf32-rounded B chunks, [kk][j*64+n]
__device__ float g_G[(size_t)N_NODES * GROW];  // per-target outer-product sums (83 MB)
__device__ float g_m[N_NODES * D];         // aggregated messages
__device__ int   g_eidx[2 * N_EDGES];      // normalized int32 edge index
__device__ int   g_cnt[N_NODES];           // edges per target
__device__ int   g_bkt[N_NODES * BKT_CAP]; // per-target edge-id buckets
__device__ int   g_is64 = 1;               // static init; detect only ever writes 0

static __forceinline__ __device__ uint32_t to_tf32(float x) { return __float_as_uint(x) + 0x1000u; }
static __forceinline__ __device__ uint32_t smem_u32(const void* p) {
    uint32_t a;
    asm("{ .reg .u64 t; cvta.to.shared.u64 t, %1; cvt.u32.u64 %0, t; }" : "=r"(a) : "l"(p));
    return a;
}
#define MMA_TF32(c, a0, a1, a2, a3, b0, b1)                                  \
    asm volatile("mma.sync.aligned.m16n8k8.row.col.f32.tf32.tf32.f32 "       \
                 "{%0,%1,%2,%3}, {%4,%5,%6,%7}, {%8,%9}, {%0,%1,%2,%3};"    \
                 : "+f"((c)[0]), "+f"((c)[1]), "+f"((c)[2]), "+f"((c)[3])    \
                 : "r"(a0), "r"(a1), "r"(a2), "r"(a3), "r"(b0), "r"(b1))

// ---------------- dtype detect + cnt zero ----------------
__global__ void detect_dtype_kernel(const unsigned* __restrict__ w) {
    int i = blockIdx.x * 256 + threadIdx.x;
    if (i < 2 * N_EDGES && (i & 1) && w[i] != 0u) g_is64 = 0;  // benign racing stores of 0
    if (i < N_NODES) g_cnt[i] = 0;
}
// normalize to int32 + bucket edges by target (replaces counting sort)
__global__ void convert_edges_kernel(const void* __restrict__ ei_raw) {
    int i = blockIdx.x * 256 + threadIdx.x;
    if (i >= 2 * N_EDGES) return;
    int v = g_is64 ? (int)((const long long*)ei_raw)[i] : ((const int*)ei_raw)[i];
    g_eidx[i] = v;
    if (i >= N_EDGES) {
        int pos = atomicAdd(&g_cnt[v], 1);
        if (pos < BKT_CAP) g_bkt[v * BKT_CAP + pos] = i - N_EDGES;
    }
}

// ---------------- prep: edge MLP (64 edges/CTA) + tf32 B chunks + zero g_m ----------------
__global__ void __launch_bounds__(256) prep_kernel(const float* __restrict__ ef,
                                                   const float* __restrict__ W1,
                                                   const float* __restrict__ b1,
                                                   const float* __restrict__ W2,
                                                   const float* __restrict__ b2) {
    int tid = threadIdx.x;
    if (blockIdx.x < MLP_BLOCKS) {
        __shared__ float W1s[EDIM * D];
        for (int i = tid; i < EDIM * D; i += 256) W1s[i] = W1[i];
        __syncthreads();
        int lane = tid & 31;
        int ebase = blockIdx.x * 64 + (tid >> 5) * 8;
        float bb0 = b1[lane], bb1 = b1[lane + 32];
#pragma unroll
        for (int i = 0; i < 8; i++) {
            int e = ebase + i;
            if (e >= N_EDGES) break;
            float a0 = bb0, a1 = bb1;
            const float* efr = ef + (size_t)e * EDIM;
#pragma unroll
            for (int f = 0; f < EDIM; f++) {
                float v = efr[f];
                a0 = fmaf(v, W1s[f * D + lane], a0);
                a1 = fmaf(v, W1s[f * D + lane + 32], a1);
            }
            g_hid[(size_t)e * D + lane]      = fmaxf(a0, 0.f);
            g_hid[(size_t)e * D + lane + 32] = fmaxf(a1, 0.f);
        }
    } else {
        // B chunk kk: B[j][n] = W2[kk*4096 + n*64 + j] (kk<64) or b2[n*64+j] (kk=64)
        int idx = (blockIdx.x - MLP_BLOCKS) * 256 + tid;
        if (idx < NCHUNK * 4096) {
            int kk = idx >> 12;
            int rem = idx & 4095;
            int j = rem >> 6, n = rem & 63;
            float v = (kk < 64) ? W2[(kk << 12) | (n << 6) | j] : b2[(n << 6) | j];
            ((uint32_t*)g_B)[idx] = to_tf32(v);
        }
        if (idx < N_NODES * D) g_m[idx] = 0.f;
    }
}

// ---------------- G-build: one CTA (256 thr) per target node, single-stage ----------------
// G[t,kk,j] = sum_{e->t} hid[e,kk]*h[src_e,j]  (kk<64);  G[t,64,j] = sum_{e->t} h[src_e,j]
__global__ void __launch_bounds__(256) gbuild_kernel(const float* __restrict__ h) {
    __shared__ float hidS[BKT_CAP][64];   // 16 KB
    __shared__ float hwS[BKT_CAP][64];    // 16 KB
    int t = blockIdx.x;
    int tid = threadIdx.x;
    int cnt = g_cnt[t];
    if (cnt > BKT_CAP) cnt = BKT_CAP;
    const int* bkt = g_bkt + t * BKT_CAP;

    // ---- stage ALL edges: 16 row-groups of 16 threads; 8 edges (hid+hw) per pass ----
    {
        int grp = tid >> 4;          // 0..15
        int q   = tid & 15;          // float4 slot in row
        int sub = grp & 7;           // edge-within-pass
        bool is_hw = (grp >= 8);
        for (int base = 0; base < cnt; base += 8) {
            int i = base + sub;
            if (i < cnt) {
                int e = bkt[i];
                if (is_hw) {
                    ((float4*)hwS[i])[q]  = ((const float4*)(h + (size_t)g_eidx[e] * D))[q];
                } else {
                    ((float4*)hidS[i])[q] = ((const float4*)(g_hid + (size_t)e * D))[q];
                }
            }
        }
    }
    __syncthreads();

    // ---- compute: thread owns k = tid>>2 (64 k's), 16 j's at jq = (tid&3)*16 ----
    int k = tid >> 2, jq = (tid & 3) * 16;
    float acc[16];
#pragma unroll
    for (int q = 0; q < 16; q++) acc[q] = 0.f;
    for (int i = 0; i < cnt; i++) {
        float hk = hidS[i][k];
        const float4* hw4 = (const float4*)(&hwS[i][jq]);
#pragma unroll
        for (int p = 0; p < 4; p++) {
            float4 v = hw4[p];
            acc[4 * p + 0] += hk * v.x;
            acc[4 * p + 1] += hk * v.y;
            acc[4 * p + 2] += hk * v.z;
            acc[4 * p + 3] += hk * v.w;
        }
    }
    float4* dst = (float4*)(g_G + (size_t)t * GROW + k * 64 + jq);
#pragma unroll
    for (int p = 0; p < 4; p++)
        dst[p] = make_float4(acc[4 * p], acc[4 * p + 1], acc[4 * p + 2], acc[4 * p + 3]);

    // ---- bias row: G[t,64,j] = sum_i hwS[i][j] ----
    if (tid < 64) {
        float s = 0.f;
        for (int i = 0; i < cnt; i++) s += hwS[i][tid];
        g_G[(size_t)t * GROW + 4096 + tid] = s;
    }
}

// ---------------- contraction GEMM: m = G(5000x4160) @ B(4160x64), K-split 7 ----------------
__global__ void __launch_bounds__(128) gemm_kernel() {
    extern __shared__ float smem[];
    float* As = smem;                       // [2][128][AS_STRIDE]
    float* Bs = smem + 2 * 128 * AS_STRIDE; // [2][64][BS_STRIDE]

    int tid = threadIdx.x;
    int w = tid >> 5, lane = tid & 31;
    int l4 = lane >> 2, c = lane & 3;
    int tile = blockIdx.x % NTILE;
    int seg  = blockIdx.x / NTILE;
    int e0 = tile * 128;
    int kbase = (seg < 5) ? seg * 9 : 45 + (seg - 5) * 10;
    int kcnt  = (seg < 5) ? 9 : 10;

    uint32_t as_addr = smem_u32(As);
    uint32_t bs_addr = smem_u32(Bs);
    int arow = e0 + tid;
    if (arow >= N_NODES) arow = N_NODES - 1;  // garbage rows discarded at epilogue
    const float* asrc_base = g_G + (size_t)arow * GROW;

#define STAGE_G(bufi, kki)                                                               \
    do {                                                                                 \
        const float* bsrc = g_B + (size_t)(kki) * 4096 + tid * 32;                       \
        uint32_t bd = bs_addr + (uint32_t)(bufi) * (BS_CHUNK * 4);                       \
        _Pragma("unroll")                                                                \
        for (int q = 0; q < 8; q++) {                                                    \
            int s = tid * 8 + q;                                                         \
            uint32_t dstb = bd + (uint32_t)((s >> 4) * BS_STRIDE + (s & 15) * 4) * 4u;   \
            asm volatile("cp.async.ca.shared.global [%0], [%1], 16;"                     \
                         :: "r"(dstb), "l"(bsrc + q * 4));                               \
        }                                                                                \
        const float* asrc = asrc_base + (kki) * 64;                                      \
        uint32_t ad = as_addr + (uint32_t)(bufi) * (128 * AS_STRIDE * 4) +               \
                      (uint32_t)tid * (AS_STRIDE * 4);                                   \
        _Pragma("unroll")                                                                \
        for (int q = 0; q < 16; q++)                                                     \
            asm volatile("cp.async.ca.shared.global [%0], [%1], 16;"                     \
                         :: "r"(ad + q * 16), "l"(asrc + q * 4));                        \
        asm volatile("cp.async.commit_group;" ::: "memory");                             \
    } while (0)

    STAGE_G(0, kbase);
    STAGE_G(1, kbase + 1);

    float acc[2][8][4];
#pragma unroll
    for (int mt = 0; mt < 2; mt++)
#pragma unroll
        for (int nt = 0; nt < 8; nt++)
#pragma unroll
            for (int q = 0; q < 4; q++) acc[mt][nt][q] = 0.f;

    for (int kk2 = 0; kk2 < kcnt; kk2++) {
        int buf = kk2 & 1;
        if (kk2 < kcnt - 1) asm volatile("cp.async.wait_group 1;" ::: "memory");
        else                asm volatile("cp.async.wait_group 0;" ::: "memory");
        __syncthreads();

        const float* ab = As + buf * (128 * AS_STRIDE);
        const float* bb = Bs + buf * BS_CHUNK;
        const float* A0 = ab + (w * 32 + l4) * AS_STRIDE;
        const float* A1 = A0 + 8 * AS_STRIDE;
        const float* A2 = A0 + 16 * AS_STRIDE;
        const float* A3 = A0 + 24 * AS_STRIDE;
#pragma unroll
        for (int kt = 0; kt < 8; kt++) {
            int kc = kt * 8 + c;
            const float* brow0 = bb + (kt * 8 + c) * BS_STRIDE + l4;
            const float* brow1 = brow0 + 4 * BS_STRIDE;
            uint32_t bw[8], bx[8];
#pragma unroll
            for (int nt = 0; nt < 8; nt++) {
                bw[nt] = __float_as_uint(brow0[nt * 8]);
                bx[nt] = __float_as_uint(brow1[nt * 8]);
            }
            {
                uint32_t a0 = to_tf32(A0[kc]);
                uint32_t a1 = to_tf32(A1[kc]);
                uint32_t a2 = to_tf32(A0[kc + 4]);
                uint32_t a3 = to_tf32(A1[kc + 4]);
#pragma unroll
                for (int nt = 0; nt < 8; nt++)
                    MMA_TF32(acc[0][nt], a0, a1, a2, a3, bw[nt], bx[nt]);
            }
            {
                uint32_t a0 = to_tf32(A2[kc]);
                uint32_t a1 = to_tf32(A3[kc]);
                uint32_t a2 = to_tf32(A2[kc + 4]);
                uint32_t a3 = to_tf32(A3[kc + 4]);
#pragma unroll
                for (int nt = 0; nt < 8; nt++)
                    MMA_TF32(acc[1][nt], a0, a1, a2, a3, bw[nt], bx[nt]);
            }
        }
        __syncthreads();
        if (kk2 + 2 < kcnt) STAGE_G(buf, kbase + kk2 + 2);
    }

    // partial-sum scatter into g_m (7 segments accumulate atomically)
#pragma unroll
    for (int mt = 0; mt < 2; mt++) {
#pragma unroll
        for (int half = 0; half < 2; half++) {
            int node = e0 + w * 32 + mt * 16 + half * 8 + l4;
            if (node < N_NODES) {
                float* dst = g_m + (size_t)node * D + 2 * c;
#pragma unroll
                for (int nt = 0; nt < 8; nt++)
                    asm volatile("red.global.add.v2.f32 [%0], {%1, %2};"
                                 :: "l"(dst + nt * 8),
                                    "f"(acc[mt][nt][half * 2]),
                                    "f"(acc[mt][nt][half * 2 + 1]) : "memory");
            }
        }
    }
#undef STAGE_G
}

// ---------------- GRU cell: 16 nodes/CTA ----------------
#define WPAD 193
__global__ void __launch_bounds__(512) gru_kernel(const float* __restrict__ h,
                                                  const float* __restrict__ W_ih,
                                                  const float* __restrict__ W_hh,
                                                  const float* __restrict__ b_ih,
                                                  const float* __restrict__ b_hh,
                                                  float* __restrict__ out) {
    extern __shared__ float smem2[];
    float* WiT = smem2;
    float* WhT = smem2 + 64 * WPAD;
    int tid = threadIdx.x;
    for (int i = tid; i < 192 * 64; i += 512) {
        int row = i >> 6, k = i & 63;
        WiT[k * WPAD + row] = W_ih[i];
        WhT[k * WPAD + row] = W_hh[i];
    }
    __syncthreads();
    int lane = tid & 31;
    int node = blockIdx.x * 16 + (tid >> 5);
    if (node >= N_NODES) return;
    const float* mrow = g_m + (size_t)node * D;
    const float* hrow = h + (size_t)node * D;
    int d0 = lane, d1 = lane + 32;
    float ir0 = b_ih[d0], ir1 = b_ih[d1];
    float iz0 = b_ih[64 + d0], iz1 = b_ih[64 + d1];
    float in0 = b_ih[128 + d0], in1 = b_ih[128 + d1];
    float hr0 = b_hh[d0], hr1 = b_hh[d1];
    float hz0 = b_hh[64 + d0], hz1 = b_hh[64 + d1];
    float hn0 = b_hh[128 + d0], hn1 = b_hh[128 + d1];
#pragma unroll 8
    for (int k = 0; k < 64; k++) {
        float mk = mrow[k], hk = hrow[k];
        const float* wi = WiT + k * WPAD;
        const float* wh = WhT + k * WPAD;
        ir0 = fmaf(mk, wi[d0], ir0);        ir1 = fmaf(mk, wi[d1], ir1);
        iz0 = fmaf(mk, wi[64 + d0], iz0);   iz1 = fmaf(mk, wi[64 + d1], iz1);
        in0 = fmaf(mk, wi[128 + d0], in0);  in1 = fmaf(mk, wi[128 + d1], in1);
        hr0 = fmaf(hk, wh[d0], hr0);        hr1 = fmaf(hk, wh[d1], hr1);
        hz0 = fmaf(hk, wh[64 + d0], hz0);   hz1 = fmaf(hk, wh[64 + d1], hz1);
        hn0 = fmaf(hk, wh[128 + d0], hn0);  hn1 = fmaf(hk, wh[128 + d1], hn1);
    }
    {
        float r = 1.f / (1.f + expf(-(ir0 + hr0)));
        float z = 1.f / (1.f + expf(-(iz0 + hz0)));
        float nn = tanhf(in0 + r * hn0);
        out[(size_t)node * D + d0] = (1.f - z) * nn + z * hrow[d0];
    }
    {
        float r = 1.f / (1.f + expf(-(ir1 + hr1)));
        float z = 1.f / (1.f + expf(-(iz1 + hz1)));
        float nn = tanhf(in1 + r * hn1);
        out[(size_t)node * D + d1] = (1.f - z) * nn + z * hrow[d1];
    }
}

// ---------------- launch ----------------
extern "C" void kernel_launch(void* const* d_in, const int* in_sizes, int n_in,
                              void* d_out, int out_size) {
    const float* h    = (const float*)d_in[0];
    const void*  ei   = (const void*)d_in[1];
    const float* ef   = (const float*)d_in[2];
    const float* W1   = (const float*)d_in[3];
    const float* b1   = (const float*)d_in[4];
    const float* W2   = (const float*)d_in[5];
    const float* b2   = (const float*)d_in[6];
    const float* W_ih = (const float*)d_in[7];
    const float* W_hh = (const float*)d_in[8];
    const float* b_ih = (const float*)d_in[9];
    const float* b_hh = (const float*)d_in[10];
    float* out = (float*)d_out;

    size_t gemm_smem = (size_t)(2 * 128 * AS_STRIDE + 2 * BS_CHUNK) * sizeof(float);  // 106496 B
    size_t gru_smem  = (size_t)(2 * 64 * WPAD) * sizeof(float);
    cudaFuncSetAttribute(gemm_kernel, cudaFuncAttributeMaxDynamicSharedMemorySize, (int)gemm_smem);
    cudaFuncSetAttribute(gru_kernel,  cudaFuncAttributeMaxDynamicSharedMemorySize, (int)gru_smem);

    detect_dtype_kernel<<<(2 * N_EDGES + 255) / 256, 256>>>((const unsigned*)ei);
    convert_edges_kernel<<<(2 * N_EDGES + 255) / 256, 256>>>(ei);
    prep_kernel<<<MLP_BLOCKS + BB_BLOCKS, 256>>>(ef, W1, b1, W2, b2);
    gbuild_kernel<<<N_NODES, 256>>>(h);
    gemm_kernel<<<NTILE * NSEG, 128, gemm_smem>>>();
    gru_kernel<<<(N_NODES + 15) / 16, 512, gru_smem>>>(h, W_ih, W_hh, b_ih, b_hh, out);
}

// round 17
// speedup vs baseline: 1.1691x; 1.1691x over previous
#include <cuda_runtime.h>
#include <cstdint>

#define N_NODES 5000
#define N_EDGES 50000
#define D 64
#define EDIM 16
#define NCHUNK 65                          // 64 W2 chunks + 1 bias chunk
#define GROW 4160                          // G row words: 65 chunks * 64
#define BS_STRIDE 72                       // padded B j-row stride (words)
#define BS_CHUNK (64 * BS_STRIDE)          // 4608 words per staged B chunk
#define AS_STRIDE 68                       // padded A row stride (words)
#define NTILE 40                           // ceil(5000/128) node tiles
#define NSEG 7                             // K segments: 5x9 + 2x10 chunks = 65; 280 CTAs (1 wave)
#define CONV_BLOCKS 391                    // ceil(100000/256)
#define MLP_BLOCKS 782                     // ceil(50000/64)
#define BB_BLOCKS 1250                     // ceil(320000/256) covers 266240 too
#define BKT_CAP 40                         // per-target bucket capacity (deg~Poisson(10))

// ---------------- scratch (static device globals; no allocation) ----------------
__device__ float g_hid[N_EDGES * D];       // relu(ef@W1+b1)
__device__ float g_B[NCHUNK * 4096];       // tf32-rounded B chunks, [kk][j*64+n]
__device__ float g_G[(size_t)N_NODES * GROW];  // per-target outer-product sums (83 MB)
__device__ float g_m[N_NODES * D];         // aggregated messages
__device__ int   g_eidx[2 * N_EDGES];      // normalized int32 edge index
__device__ int   g_cnt[N_NODES];           // edges per target
__device__ int   g_bkt[N_NODES * BKT_CAP]; // per-target edge-id buckets
__device__ int   g_is64 = 1;               // static init; detect only ever writes 0

static __forceinline__ __device__ uint32_t to_tf32(float x) { return __float_as_uint(x) + 0x1000u; }
static __forceinline__ __device__ uint32_t smem_u32(const void* p) {
    uint32_t a;
    asm("{ .reg .u64 t; cvta.to.shared.u64 t, %1; cvt.u32.u64 %0, t; }" : "=r"(a) : "l"(p));
    return a;
}
#define MMA_TF32(c, a0, a1, a2, a3, b0, b1)                                  \
    asm volatile("mma.sync.aligned.m16n8k8.row.col.f32.tf32.tf32.f32 "       \
                 "{%0,%1,%2,%3}, {%4,%5,%6,%7}, {%8,%9}, {%0,%1,%2,%3};"    \
                 : "+f"((c)[0]), "+f"((c)[1]), "+f"((c)[2]), "+f"((c)[3])    \
                 : "r"(a0), "r"(a1), "r"(a2), "r"(a3), "r"(b0), "r"(b1))

// ---------------- dtype detect + cnt zero ----------------
__global__ void detect_dtype_kernel(const unsigned* __restrict__ w) {
    int i = blockIdx.x * 256 + threadIdx.x;
    if (i < 2 * N_EDGES && (i & 1) && w[i] != 0u) g_is64 = 0;  // benign racing stores of 0
    if (i < N_NODES) g_cnt[i] = 0;
}

// ---------------- fused: convert+bucket | edge MLP | B chunks + zero g_m ----------------
__global__ void __launch_bounds__(256) convprep_kernel(const void* __restrict__ ei_raw,
                                                       const float* __restrict__ ef,
                                                       const float* __restrict__ W1,
                                                       const float* __restrict__ b1,
                                                       const float* __restrict__ W2,
                                                       const float* __restrict__ b2) {
    int tid = threadIdx.x;
    if (blockIdx.x < CONV_BLOCKS) {
        // normalize to int32 + bucket edges by target
        int i = blockIdx.x * 256 + tid;
        if (i >= 2 * N_EDGES) return;
        int v = g_is64 ? (int)((const long long*)ei_raw)[i] : ((const int*)ei_raw)[i];
        g_eidx[i] = v;
        if (i >= N_EDGES) {
            int pos = atomicAdd(&g_cnt[v], 1);
            if (pos < BKT_CAP) g_bkt[v * BKT_CAP + pos] = i - N_EDGES;
        }
    } else if (blockIdx.x < CONV_BLOCKS + MLP_BLOCKS) {
        __shared__ float W1s[EDIM * D];
        for (int i = tid; i < EDIM * D; i += 256) W1s[i] = W1[i];
        __syncthreads();
        int lane = tid & 31;
        int ebase = (blockIdx.x - CONV_BLOCKS) * 64 + (tid >> 5) * 8;
        float bb0 = b1[lane], bb1 = b1[lane + 32];
#pragma unroll
        for (int i = 0; i < 8; i++) {
            int e = ebase + i;
            if (e >= N_EDGES) break;
            float a0 = bb0, a1 = bb1;
            const float* efr = ef + (size_t)e * EDIM;
#pragma unroll
            for (int f = 0; f < EDIM; f++) {
                float v = efr[f];
                a0 = fmaf(v, W1s[f * D + lane], a0);
                a1 = fmaf(v, W1s[f * D + lane + 32], a1);
            }
            g_hid[(size_t)e * D + lane]      = fmaxf(a0, 0.f);
            g_hid[(size_t)e * D + lane + 32] = fmaxf(a1, 0.f);
        }
    } else {
        // B chunk kk: B[j][n] = W2[kk*4096 + n*64 + j] (kk<64) or b2[n*64+j] (kk=64)
        int idx = (blockIdx.x - CONV_BLOCKS - MLP_BLOCKS) * 256 + tid;
        if (idx < NCHUNK * 4096) {
            int kk = idx >> 12;
            int rem = idx & 4095;
            int j = rem >> 6, n = rem & 63;
            float v = (kk < 64) ? W2[(kk << 12) | (n << 6) | j] : b2[(n << 6) | j];
            ((uint32_t*)g_B)[idx] = to_tf32(v);
        }
        if (idx < N_NODES * D) g_m[idx] = 0.f;
    }
}

// ---------------- G-build v3: 128 thr/node, cp.async stage, 2k x 16j broadcast map ----------
// G[t,kk,j] = sum_{e->t} hid[e,kk]*h[src_e,j]  (kk<64);  G[t,64,j] = sum_{e->t} h[src_e,j]
__global__ void __launch_bounds__(128) gbuild_kernel(const float* __restrict__ h) {
    __shared__ float hidS[BKT_CAP][64];   // 10.24 KB
    __shared__ float hwS[BKT_CAP][64];    // 10.24 KB
    int t = blockIdx.x;
    int tid = threadIdx.x;
    int cnt = g_cnt[t];
    if (cnt > BKT_CAP) cnt = BKT_CAP;
    const int* bkt = g_bkt + t * BKT_CAP;

    // ---- stage ALL edges via cp.async: 8 half-rows per pass (4 hid-edges + 4 hw-edges) ----
    {
        int q = tid & 15;              // float4 slot within 64-float row
        int sub = (tid >> 4) & 3;      // edge offset within pass
        bool is_hw = (tid >= 64);
        for (int base = 0; base < cnt; base += 4) {
            int i = base + sub;
            if (i < cnt) {
                int e = bkt[i];
                const float* src = is_hw ? (h + (size_t)g_eidx[e] * D + q * 4)
                                         : (g_hid + (size_t)e * D + q * 4);
                uint32_t dst = smem_u32(is_hw ? &hwS[i][q * 4] : &hidS[i][q * 4]);
                asm volatile("cp.async.ca.shared.global [%0], [%1], 16;"
                             :: "r"(dst), "l"(src));
            }
        }
        asm volatile("cp.async.commit_group;" ::: "memory");
        asm volatile("cp.async.wait_group 0;" ::: "memory");
    }
    __syncthreads();

    // ---- compute: thread owns k0=tid>>2, k1=k0+32, 16 j's at jq=(tid&3)*16 ----
    int k0 = tid >> 2, k1 = k0 + 32, jq = (tid & 3) * 16;
    float a0[16], a1[16];
#pragma unroll
    for (int q = 0; q < 16; q++) { a0[q] = 0.f; a1[q] = 0.f; }
    for (int i = 0; i < cnt; i++) {
        float h0 = hidS[i][k0];
        float h1 = hidS[i][k1];
        const float4* hw4 = (const float4*)(&hwS[i][jq]);
#pragma unroll
        for (int p = 0; p < 4; p++) {
            float4 v = hw4[p];
            a0[4 * p + 0] += h0 * v.x; a0[4 * p + 1] += h0 * v.y;
            a0[4 * p + 2] += h0 * v.z; a0[4 * p + 3] += h0 * v.w;
            a1[4 * p + 0] += h1 * v.x; a1[4 * p + 1] += h1 * v.y;
            a1[4 * p + 2] += h1 * v.z; a1[4 * p + 3] += h1 * v.w;
        }
    }
    float4* d0 = (float4*)(g_G + (size_t)t * GROW + k0 * 64 + jq);
    float4* d1 = (float4*)(g_G + (size_t)t * GROW + k1 * 64 + jq);
#pragma unroll
    for (int p = 0; p < 4; p++) {
        d0[p] = make_float4(a0[4 * p], a0[4 * p + 1], a0[4 * p + 2], a0[4 * p + 3]);
        d1[p] = make_float4(a1[4 * p], a1[4 * p + 1], a1[4 * p + 2], a1[4 * p + 3]);
    }
    // ---- bias row: G[t,64,j] = sum_i hwS[i][j] ----
    if (tid < 64) {
        float s = 0.f;
        for (int i = 0; i < cnt; i++) s += hwS[i][tid];
        g_G[(size_t)t * GROW + 4096 + tid] = s;
    }
}

// ---------------- contraction GEMM: m = G(5000x4160) @ B(4160x64), K-split 7 ----------------
__global__ void __launch_bounds__(128) gemm_kernel() {
    extern __shared__ float smem[];
    float* As = smem;                       // [2][128][AS_STRIDE]
    float* Bs = smem + 2 * 128 * AS_STRIDE; // [2][64][BS_STRIDE]

    int tid = threadIdx.x;
    int w = tid >> 5, lane = tid & 31;
    int l4 = lane >> 2, c = lane & 3;
    int tile = blockIdx.x % NTILE;
    int seg  = blockIdx.x / NTILE;
    int e0 = tile * 128;
    int kbase = (seg < 5) ? seg * 9 : 45 + (seg - 5) * 10;
    int kcnt  = (seg < 5) ? 9 : 10;

    uint32_t as_addr = smem_u32(As);
    uint32_t bs_addr = smem_u32(Bs);
    int arow = e0 + tid;
    if (arow >= N_NODES) arow = N_NODES - 1;  // garbage rows discarded at epilogue
    const float* asrc_base = g_G + (size_t)arow * GROW;

#define STAGE_G(bufi, kki)                                                               \
    do {                                                                                 \
        const float* bsrc = g_B + (size_t)(kki) * 4096 + tid * 32;                       \
        uint32_t bd = bs_addr + (uint32_t)(bufi) * (BS_CHUNK * 4);                       \
        _Pragma("unroll")                                                                \
        for (int q = 0; q < 8; q++) {                                                    \
            int s = tid * 8 + q;                                                         \
            uint32_t dstb = bd + (uint32_t)((s >> 4) * BS_STRIDE + (s & 15) * 4) * 4u;   \
            asm volatile("cp.async.ca.shared.global [%0], [%1], 16;"                     \
                         :: "r"(dstb), "l"(bsrc + q * 4));                               \
        }                                                                                \
        const float* asrc = asrc_base + (kki) * 64;                                      \
        uint32_t ad = as_addr + (uint32_t)(bufi) * (128 * AS_STRIDE * 4) +               \
                      (uint32_t)tid * (AS_STRIDE * 4);                                   \
        _Pragma("unroll")                                                                \
        for (int q = 0; q < 16; q++)                                                     \
            asm volatile("cp.async.ca.shared.global [%0], [%1], 16;"                     \
                         :: "r"(ad + q * 16), "l"(asrc + q * 4));                        \
        asm volatile("cp.async.commit_group;" ::: "memory");                             \
    } while (0)

    STAGE_G(0, kbase);
    STAGE_G(1, kbase + 1);

    float acc[2][8][4];
#pragma unroll
    for (int mt = 0; mt < 2; mt++)
#pragma unroll
        for (int nt = 0; nt < 8; nt++)
#pragma unroll
            for (int q = 0; q < 4; q++) acc[mt][nt][q] = 0.f;

    for (int kk2 = 0; kk2 < kcnt; kk2++) {
        int buf = kk2 & 1;
        if (kk2 < kcnt - 1) asm volatile("cp.async.wait_group 1;" ::: "memory");
        else                asm volatile("cp.async.wait_group 0;" ::: "memory");
        __syncthreads();

        const float* ab = As + buf * (128 * AS_STRIDE);
        const float* bb = Bs + buf * BS_CHUNK;
        const float* A0 = ab + (w * 32 + l4) * AS_STRIDE;
        const float* A1 = A0 + 8 * AS_STRIDE;
        const float* A2 = A0 + 16 * AS_STRIDE;
        const float* A3 = A0 + 24 * AS_STRIDE;
#pragma unroll
        for (int kt = 0; kt < 8; kt++) {
            int kc = kt * 8 + c;
            const float* brow0 = bb + (kt * 8 + c) * BS_STRIDE + l4;
            const float* brow1 = brow0 + 4 * BS_STRIDE;
            uint32_t bw[8], bx[8];
#pragma unroll
            for (int nt = 0; nt < 8; nt++) {
                bw[nt] = __float_as_uint(brow0[nt * 8]);
                bx[nt] = __float_as_uint(brow1[nt * 8]);
            }
            {
                uint32_t a0 = to_tf32(A0[kc]);
                uint32_t a1 = to_tf32(A1[kc]);
                uint32_t a2 = to_tf32(A0[kc + 4]);
                uint32_t a3 = to_tf32(A1[kc + 4]);
#pragma unroll
                for (int nt = 0; nt < 8; nt++)
                    MMA_TF32(acc[0][nt], a0, a1, a2, a3, bw[nt], bx[nt]);
            }
            {
                uint32_t a0 = to_tf32(A2[kc]);
                uint32_t a1 = to_tf32(A3[kc]);
                uint32_t a2 = to_tf32(A2[kc + 4]);
                uint32_t a3 = to_tf32(A3[kc + 4]);
#pragma unroll
                for (int nt = 0; nt < 8; nt++)
                    MMA_TF32(acc[1][nt], a0, a1, a2, a3, bw[nt], bx[nt]);
            }
        }
        __syncthreads();
        if (kk2 + 2 < kcnt) STAGE_G(buf, kbase + kk2 + 2);
    }

    // partial-sum scatter into g_m (7 segments accumulate atomically)
#pragma unroll
    for (int mt = 0; mt < 2; mt++) {
#pragma unroll
        for (int half = 0; half < 2; half++) {
            int node = e0 + w * 32 + mt * 16 + half * 8 + l4;
            if (node < N_NODES) {
                float* dst = g_m + (size_t)node * D + 2 * c;
#pragma unroll
                for (int nt = 0; nt < 8; nt++)
                    asm volatile("red.global.add.v2.f32 [%0], {%1, %2};"
                                 :: "l"(dst + nt * 8),
                                    "f"(acc[mt][nt][half * 2]),
                                    "f"(acc[mt][nt][half * 2 + 1]) : "memory");
            }
        }
    }
#undef STAGE_G
}

// ---------------- GRU cell: 16 nodes/CTA ----------------
#define WPAD 193
__global__ void __launch_bounds__(512) gru_kernel(const float* __restrict__ h,
                                                  const float* __restrict__ W_ih,
                                                  const float* __restrict__ W_hh,
                                                  const float* __restrict__ b_ih,
                                                  const float* __restrict__ b_hh,
                                                  float* __restrict__ out) {
    extern __shared__ float smem2[];
    float* WiT = smem2;
    float* WhT = smem2 + 64 * WPAD;
    int tid = threadIdx.x;
    for (int i = tid; i < 192 * 64; i += 512) {
        int row = i >> 6, k = i & 63;
        WiT[k * WPAD + row] = W_ih[i];
        WhT[k * WPAD + row] = W_hh[i];
    }
    __syncthreads();
    int lane = tid & 31;
    int node = blockIdx.x * 16 + (tid >> 5);
    if (node >= N_NODES) return;
    const float* mrow = g_m + (size_t)node * D;
    const float* hrow = h + (size_t)node * D;
    int d0 = lane, d1 = lane + 32;
    float ir0 = b_ih[d0], ir1 = b_ih[d1];
    float iz0 = b_ih[64 + d0], iz1 = b_ih[64 + d1];
    float in0 = b_ih[128 + d0], in1 = b_ih[128 + d1];
    float hr0 = b_hh[d0], hr1 = b_hh[d1];
    float hz0 = b_hh[64 + d0], hz1 = b_hh[64 + d1];
    float hn0 = b_hh[128 + d0], hn1 = b_hh[128 + d1];
#pragma unroll 8
    for (int k = 0; k < 64; k++) {
        float mk = mrow[k], hk = hrow[k];
        const float* wi = WiT + k * WPAD;
        const float* wh = WhT + k * WPAD;
        ir0 = fmaf(mk, wi[d0], ir0);        ir1 = fmaf(mk, wi[d1], ir1);
        iz0 = fmaf(mk, wi[64 + d0], iz0);   iz1 = fmaf(mk, wi[64 + d1], iz1);
        in0 = fmaf(mk, wi[128 + d0], in0);  in1 = fmaf(mk, wi[128 + d1], in1);
        hr0 = fmaf(hk, wh[d0], hr0);        hr1 = fmaf(hk, wh[d1], hr1);
        hz0 = fmaf(hk, wh[64 + d0], hz0);   hz1 = fmaf(hk, wh[64 + d1], hz1);
        hn0 = fmaf(hk, wh[128 + d0], hn0);  hn1 = fmaf(hk, wh[128 + d1], hn1);
    }
    {
        float r = 1.f / (1.f + expf(-(ir0 + hr0)));
        float z = 1.f / (1.f + expf(-(iz0 + hz0)));
        float nn = tanhf(in0 + r * hn0);
        out[(size_t)node * D + d0] = (1.f - z) * nn + z * hrow[d0];
    }
    {
        float r = 1.f / (1.f + expf(-(ir1 + hr1)));
        float z = 1.f / (1.f + expf(-(iz1 + hz1)));
        float nn = tanhf(in1 + r * hn1);
        out[(size_t)node * D + d1] = (1.f - z) * nn + z * hrow[d1];
    }
}

// ---------------- launch ----------------
extern "C" void kernel_launch(void* const* d_in, const int* in_sizes, int n_in,
                              void* d_out, int out_size) {
    const float* h    = (const float*)d_in[0];
    const void*  ei   = (const void*)d_in[1];
    const float* ef   = (const float*)d_in[2];
    const float* W1   = (const float*)d_in[3];
    const float* b1   = (const float*)d_in[4];
    const float* W2   = (const float*)d_in[5];
    const float* b2   = (const float*)d_in[6];
    const float* W_ih = (const float*)d_in[7];
    const float* W_hh = (const float*)d_in[8];
    const float* b_ih = (const float*)d_in[9];
    const float* b_hh = (const float*)d_in[10];
    float* out = (float*)d_out;

    size_t gemm_smem = (size_t)(2 * 128 * AS_STRIDE + 2 * BS_CHUNK) * sizeof(float);  // 106496 B
    size_t gru_smem  = (size_t)(2 * 64 * WPAD) * sizeof(float);
    cudaFuncSetAttribute(gemm_kernel, cudaFuncAttributeMaxDynamicSharedMemorySize, (int)gemm_smem);
    cudaFuncSetAttribute(gru_kernel,  cudaFuncAttributeMaxDynamicSharedMemorySize, (int)gru_smem);

    detect_dtype_kernel<<<(2 * N_EDGES + 255) / 256, 256>>>((const unsigned*)ei);
    convprep_kernel<<<CONV_BLOCKS + MLP_BLOCKS + BB_BLOCKS, 256>>>(ei, ef, W1, b1, W2, b2);
    gbuild_kernel<<<N_NODES, 128>>>(h);
    gemm_kernel<<<NTILE * NSEG, 128, gemm_smem>>>();
    gru_kernel<<<(N_NODES + 15) / 16, 512, gru_smem>>>(h, W_ih, W_hh, b_ih, b_hh, out);
}